// round 7
// baseline (speedup 1.0000x reference)
#include <cuda_runtime.h>

#define BATCHES 8
#define N_PER 8192
#define M_PER 2048
#define C_FEAT 32
#define K 32
#define NCH (3 + C_FEAT)              // 35
#define THREADS 960
#define WARPS (THREADS / 32)          // 30
#define CHUNKS 18                     // 18*8 = 144 CTAs, 1 per SM
#define Q_PER_CHUNK 114               // covers 2048
#define M_TOT (BATCHES * M_PER)              // 16384
#define FEAT_ELEMS ((size_t)M_TOT * NCH * K) // 18350080

// smem word layout:
//  sxy   [0, 16384)                      float2[8192]
//  sz    [16384, 24576)                  float[8192]
//  tiles [24576, +WARPS*1024)            32x32 floats per warp, XOR-swizzled
//  slots [.., +WARPS*64)                 2 queries x 32 slots per warp
//  qctr  [last]
#define OFF_SZ    16384
#define OFF_TILE  24576
#define OFF_WS    (OFF_TILE + WARPS * 1024)        // 55296
#define OFF_QCTR  (OFF_WS + WARPS * 64)            // 57216
#define SMEM_BYTES ((OFF_QCTR + 4) * 4)            // ~228.9KB

// JAX compares d2 < f32(0.04) = 0.039999999105930328f (NOT 0.2f*0.2f)
#define R2 ((float)(0.2 * 0.2))

__device__ __forceinline__ void emit_query(
    int m, int cnt, const int* ws,
    float qx, float qy, float qz,
    const float2* sxy, const float* sz, float* tile,
    const float* features, int bbase, float* __restrict__ out,
    int lane, int j4, int cc)
{
    const bool empty = (cnt == 0);
    const int c = cnt < K ? cnt : K;
    const float sc = empty ? 0.0f : 1.0f;

    // lane s's neighbor index (reference padding semantics)
    int i = 0;
    if (!empty) i = (lane < c) ? ws[lane] : ws[0];

    // coalesced feature gather -> XOR-swizzled 4KB warp tile (STS.128)
    #pragma unroll
    for (int r = 0; r < 8; r++) {
        const int s  = 4 * r + j4;
        const int is = __shfl_sync(0xffffffffu, i, s);
        float4 v = __ldg((const float4*)(features +
                         (size_t)(bbase + is) * C_FEAT) + cc);
        v.x *= sc; v.y *= sc; v.z *= sc; v.w *= sc;
        *(float4*)(tile + s * 32 + ((4 * cc) ^ (4 * (s & 7)))) = v;
    }

    // xyz channels (lane = k)
    const float2 pxy = sxy[i];
    const float  pz  = sz[i];
    const size_t ob = (size_t)m * (NCH * K);
    out[ob + 0 * K + lane] = (pxy.x - qx) * sc;
    out[ob + 1 * K + lane] = (pxy.y - qy) * sc;
    out[ob + 2 * K + lane] = (pz    - qz) * sc;

    __syncwarp();

    // feature channels: lane k reads its tile row (LDS.128), coalesced STG
    #pragma unroll
    for (int t = 0; t < 8; t++) {
        const float4 v = *(const float4*)(tile + lane * 32 +
                                          ((4 * t) ^ (4 * (lane & 7))));
        out[ob + (size_t)(3 + 4 * t + 0) * K + lane] = v.x;
        out[ob + (size_t)(3 + 4 * t + 1) * K + lane] = v.y;
        out[ob + (size_t)(3 + 4 * t + 2) * K + lane] = v.z;
        out[ob + (size_t)(3 + 4 * t + 3) * K + lane] = v.w;
    }

    // Output dtype is float32: idx stored as float (0..8191 exact).
    out[FEAT_ELEMS + (size_t)m * K + lane] = empty ? 0.0f : (float)i;
    __syncwarp();
}

__global__ __launch_bounds__(THREADS, 1)
void sqag_kernel(const float* __restrict__ xyz,
                 const float* __restrict__ new_xyz,
                 const float* __restrict__ features,
                 float* __restrict__ out)
{
    extern __shared__ float smem[];
    float2* sxy   = (float2*)smem;
    float*  sz    = smem + OFF_SZ;
    int*    slots = (int*)(smem + OFF_WS);
    int*    qctr  = (int*)(smem + OFF_QCTR);

    const int batch = blockIdx.y;
    const int bbase = batch * N_PER;
    const float* bx = xyz + (size_t)bbase * 3;

    if (threadIdx.x == 0) *qctr = 0;

    // Stage this batch's xyz into SMEM (float2 xy + float z).
    for (int p = threadIdx.x; p < N_PER; p += THREADS) {
        const float* src = bx + 3 * p;
        sxy[p] = make_float2(src[0], src[1]);
        sz[p]  = src[2];
    }
    __syncthreads();

    const int wid  = threadIdx.x >> 5;
    const int lane = threadIdx.x & 31;
    int*   ws0  = slots + wid * 64;
    int*   ws1  = ws0 + 32;
    float* tile = smem + OFF_TILE + wid * 1024;
    const unsigned lanemask_lt = (1u << lane) - 1u;
    const int j4 = lane >> 3;   // 0..3 (row-in-round for gather)
    const int cc = lane & 7;    // 0..7 (float4 chunk within feature row)

    const int q_start = blockIdx.x * Q_PER_CHUNK;
    const int nq = min(Q_PER_CHUNK, M_PER - q_start);

    for (;;) {
        int qt;
        if (lane == 0) qt = atomicAdd(qctr, 2);
        qt = __shfl_sync(0xffffffffu, qt, 0);
        if (qt >= nq) break;
        const bool valid1 = (qt + 1 < nq);

        const int m0 = batch * M_PER + q_start + qt;
        const int m1 = m0 + (valid1 ? 1 : 0);
        const float* qp0 = new_xyz + (size_t)m0 * 3;
        const float* qp1 = new_xyz + (size_t)m1 * 3;
        const float qx0 = qp0[0], qy0 = qp0[1], qz0 = qp0[2];
        const float qx1 = qp1[0], qy1 = qp1[1], qz1 = qp1[2];

        // ---- shared-load dual-query scan: 64 candidates per exit check
        int cnt0 = 0;
        int cnt1 = valid1 ? 0 : K;
        for (int j0 = 0; j0 < N_PER && (cnt0 < K || cnt1 < K); j0 += 64) {
            const float2 xyA = sxy[j0 + lane];
            const float2 xyB = sxy[j0 + 32 + lane];
            const float  zA  = sz[j0 + lane];
            const float  zB  = sz[j0 + 32 + lane];

            if (cnt0 < K) {   // warp-uniform
                const float dxA = xyA.x - qx0, dyA = xyA.y - qy0, dzA = zA - qz0;
                const float d2A = __fadd_rn(__fadd_rn(__fmul_rn(dxA, dxA),
                                                      __fmul_rn(dyA, dyA)),
                                            __fmul_rn(dzA, dzA));
                const float dxB = xyB.x - qx0, dyB = xyB.y - qy0, dzB = zB - qz0;
                const float d2B = __fadd_rn(__fadd_rn(__fmul_rn(dxB, dxB),
                                                      __fmul_rn(dyB, dyB)),
                                            __fmul_rn(dzB, dzB));
                const unsigned mA = __ballot_sync(0xffffffffu, d2A < R2);
                const unsigned mB = __ballot_sync(0xffffffffu, d2B < R2);
                if (mA & (1u << lane)) {
                    const int pos = cnt0 + __popc(mA & lanemask_lt);
                    if (pos < K) ws0[pos] = j0 + lane;
                }
                const int c1 = cnt0 + __popc(mA);
                if (mB & (1u << lane)) {
                    const int pos = c1 + __popc(mB & lanemask_lt);
                    if (pos < K) ws0[pos] = j0 + 32 + lane;
                }
                cnt0 = c1 + __popc(mB);
            }
            if (cnt1 < K) {   // warp-uniform
                const float dxA = xyA.x - qx1, dyA = xyA.y - qy1, dzA = zA - qz1;
                const float d2A = __fadd_rn(__fadd_rn(__fmul_rn(dxA, dxA),
                                                      __fmul_rn(dyA, dyA)),
                                            __fmul_rn(dzA, dzA));
                const float dxB = xyB.x - qx1, dyB = xyB.y - qy1, dzB = zB - qz1;
                const float d2B = __fadd_rn(__fadd_rn(__fmul_rn(dxB, dxB),
                                                      __fmul_rn(dyB, dyB)),
                                            __fmul_rn(dzB, dzB));
                const unsigned mA = __ballot_sync(0xffffffffu, d2A < R2);
                const unsigned mB = __ballot_sync(0xffffffffu, d2B < R2);
                if (mA & (1u << lane)) {
                    const int pos = cnt1 + __popc(mA & lanemask_lt);
                    if (pos < K) ws1[pos] = j0 + lane;
                }
                const int c1 = cnt1 + __popc(mA);
                if (mB & (1u << lane)) {
                    const int pos = c1 + __popc(mB & lanemask_lt);
                    if (pos < K) ws1[pos] = j0 + 32 + lane;
                }
                cnt1 = c1 + __popc(mB);
            }
        }
        __syncwarp();

        emit_query(m0, cnt0, ws0, qx0, qy0, qz0, sxy, sz, tile,
                   features, bbase, out, lane, j4, cc);
        if (valid1)
            emit_query(m1, cnt1, ws1, qx1, qy1, qz1, sxy, sz, tile,
                       features, bbase, out, lane, j4, cc);
    }
}

extern "C" void kernel_launch(void* const* d_in, const int* in_sizes, int n_in,
                              void* d_out, int out_size)
{
    const float* xyz      = (const float*)d_in[0];
    // d_in[1]: xyz_batch_cnt (constant N_PER, unused)
    const float* new_xyz  = (const float*)d_in[2];
    // d_in[3]: new_xyz_batch_cnt (constant M_PER, unused)
    const float* features = (const float*)d_in[4];

    cudaFuncSetAttribute(sqag_kernel,
                         cudaFuncAttributeMaxDynamicSharedMemorySize, SMEM_BYTES);

    dim3 grid(CHUNKS, BATCHES);
    sqag_kernel<<<grid, THREADS, SMEM_BYTES>>>(xyz, new_xyz, features, (float*)d_out);
}

// round 8
// speedup vs baseline: 1.2337x; 1.2337x over previous
#include <cuda_runtime.h>

#define BATCHES 8
#define N_PER 8192
#define M_PER 2048
#define C_FEAT 32
#define K 32
#define NCH (3 + C_FEAT)              // 35
#define THREADS 960
#define WARPS (THREADS / 32)          // 30
#define CHUNKS 18                     // 18*8 = 144 CTAs, 1 per SM
#define Q_PER_CHUNK 114               // covers 2048
#define M_TOT (BATCHES * M_PER)              // 16384
#define FEAT_ELEMS ((size_t)M_TOT * NCH * K) // 18350080

// smem word layout:
//  sx    [0, 8192)       sy [8192,16384)   sz [16384,24576)
//  tiles [24576, +WARPS*1024)   32x32 floats per warp, XOR-swizzled
//  slots [.., +WARPS*32)
//  qctr  [last]
#define OFF_SY    8192
#define OFF_SZ    16384
#define OFF_TILE  24576
#define OFF_WS    (OFF_TILE + WARPS * 1024)        // 55296
#define OFF_QCTR  (OFF_WS + WARPS * 32)            // 56256
#define SMEM_BYTES ((OFF_QCTR + 4) * 4)            // ~225KB

// JAX compares d2 < f32(0.04) = 0.039999999105930328f (NOT 0.2f*0.2f)
#define R2 ((float)(0.2 * 0.2))

__device__ __forceinline__ unsigned long long pack2(float a, float b) {
    unsigned long long r;
    asm("mov.b64 %0, {%1, %2};" : "=l"(r) : "f"(a), "f"(b));
    return r;
}
__device__ __forceinline__ void unpack2(unsigned long long v, float& a, float& b) {
    asm("mov.b64 {%0, %1}, %2;" : "=f"(a), "=f"(b) : "l"(v));
}
__device__ __forceinline__ unsigned long long add2(unsigned long long a, unsigned long long b) {
    unsigned long long r;
    asm("add.rn.f32x2 %0, %1, %2;" : "=l"(r) : "l"(a), "l"(b));
    return r;
}
__device__ __forceinline__ unsigned long long mul2(unsigned long long a, unsigned long long b) {
    unsigned long long r;
    asm("mul.rn.f32x2 %0, %1, %2;" : "=l"(r) : "l"(a), "l"(b));
    return r;
}

__global__ __launch_bounds__(THREADS, 1)
void sqag_kernel(const float* __restrict__ xyz,
                 const float* __restrict__ new_xyz,
                 const float* __restrict__ features,
                 float* __restrict__ out)
{
    extern __shared__ float smem[];
    float* sx = smem;
    float* sy = smem + OFF_SY;
    float* sz = smem + OFF_SZ;
    int*   slots = (int*)(smem + OFF_WS);
    int*   qctr  = (int*)(smem + OFF_QCTR);

    const int batch = blockIdx.y;
    const int bbase = batch * N_PER;
    const float* bx = xyz + (size_t)bbase * 3;

    if (threadIdx.x == 0) *qctr = 0;

    // Stage this batch's xyz into SMEM as SoA (float4-loadable).
    for (int p = threadIdx.x; p < N_PER; p += THREADS) {
        const float* src = bx + 3 * p;
        sx[p] = src[0];
        sy[p] = src[1];
        sz[p] = src[2];
    }
    __syncthreads();

    const int wid  = threadIdx.x >> 5;
    const int lane = threadIdx.x & 31;
    int*   ws   = slots + wid * K;
    float* tile = smem + OFF_TILE + wid * 1024;
    const unsigned lanemask_lt = (1u << lane) - 1u;
    const int j4 = lane >> 3;   // 0..3 (row-in-round for gather)
    const int cc = lane & 7;    // 0..7 (float4 chunk within feature row)

    const int q_start = blockIdx.x * Q_PER_CHUNK;
    const int nq = min(Q_PER_CHUNK, M_PER - q_start);

    for (;;) {
        int qt;
        if (lane == 0) qt = atomicAdd(qctr, 1);
        qt = __shfl_sync(0xffffffffu, qt, 0);
        if (qt >= nq) break;

        const int m = batch * M_PER + q_start + qt;
        const float* qp = new_xyz + (size_t)m * 3;
        const float qx = qp[0], qy = qp[1], qz = qp[2];
        // packed (-q,-q): x + (-q) is bit-identical to x - q (IEEE rn)
        const unsigned long long nqx = pack2(-qx, -qx);
        const unsigned long long nqy = pack2(-qy, -qy);
        const unsigned long long nqz = pack2(-qz, -qz);

        // ---- scan: lane owns candidates j0+4*lane+t, packed f32x2 math
        int cnt = 0;  // warp-uniform
        for (int j0 = 0; j0 < N_PER && cnt < K; j0 += 128) {
            const int jb = j0 + 4 * lane;
            const float4 xv = *(const float4*)(sx + jb);
            const float4 yv = *(const float4*)(sy + jb);
            const float4 zv = *(const float4*)(sz + jb);

            // pair 0: candidates t=0,1
            const unsigned long long dx0 = add2(pack2(xv.x, xv.y), nqx);
            const unsigned long long dy0 = add2(pack2(yv.x, yv.y), nqy);
            const unsigned long long dz0 = add2(pack2(zv.x, zv.y), nqz);
            const unsigned long long s0 =
                add2(add2(mul2(dx0, dx0), mul2(dy0, dy0)), mul2(dz0, dz0));
            // pair 1: candidates t=2,3
            const unsigned long long dx1 = add2(pack2(xv.z, xv.w), nqx);
            const unsigned long long dy1 = add2(pack2(yv.z, yv.w), nqy);
            const unsigned long long dz1 = add2(pack2(zv.z, zv.w), nqz);
            const unsigned long long s1 =
                add2(add2(mul2(dx1, dx1), mul2(dy1, dy1)), mul2(dz1, dz1));

            float d0, d1, d2_, d3;
            unpack2(s0, d0, d1);
            unpack2(s1, d2_, d3);
            const bool b0 = d0 < R2, b1 = d1 < R2, b2 = d2_ < R2, b3 = d3 < R2;
            const unsigned m0 = __ballot_sync(0xffffffffu, b0);
            const unsigned m1 = __ballot_sync(0xffffffffu, b1);
            const unsigned m2 = __ballot_sync(0xffffffffu, b2);
            const unsigned m3 = __ballot_sync(0xffffffffu, b3);

            // global index order j = j0 + 4*L + t
            const int below = __popc(m0 & lanemask_lt) + __popc(m1 & lanemask_lt)
                            + __popc(m2 & lanemask_lt) + __popc(m3 & lanemask_lt);
            int pos = cnt + below;
            if (b0) { if (pos < K) ws[pos] = jb + 0; pos++; }
            if (b1) { if (pos < K) ws[pos] = jb + 1; pos++; }
            if (b2) { if (pos < K) ws[pos] = jb + 2; pos++; }
            if (b3) { if (pos < K) ws[pos] = jb + 3; }
            cnt += __popc(m0) + __popc(m1) + __popc(m2) + __popc(m3);
        }
        __syncwarp();

        const bool empty = (cnt == 0);
        const int c = cnt < K ? cnt : K;
        const float sc = empty ? 0.0f : 1.0f;

        // lane s's neighbor index (reference padding semantics)
        int i = 0;
        if (!empty) i = (lane < c) ? ws[lane] : ws[0];

        // ---- coalesced feature gather -> XOR-swizzled 4KB warp tile (STS.128)
        #pragma unroll
        for (int r = 0; r < 8; r++) {
            const int s  = 4 * r + j4;
            const int is = __shfl_sync(0xffffffffu, i, s);
            float4 v = __ldg((const float4*)(features +
                             (size_t)(bbase + is) * C_FEAT) + cc);
            v.x *= sc; v.y *= sc; v.z *= sc; v.w *= sc;
            *(float4*)(tile + s * 32 + ((4 * cc) ^ (4 * (s & 7)))) = v;
        }

        // ---- xyz channels (lane = k)
        const float px = sx[i], py = sy[i], pz = sz[i];
        const size_t ob = (size_t)m * (NCH * K);
        out[ob + 0 * K + lane] = (px - qx) * sc;
        out[ob + 1 * K + lane] = (py - qy) * sc;
        out[ob + 2 * K + lane] = (pz - qz) * sc;

        __syncwarp();

        // ---- feature channels: lane k reads its tile row (LDS.128), coalesced STG
        #pragma unroll
        for (int t = 0; t < 8; t++) {
            const float4 v = *(const float4*)(tile + lane * 32 +
                                              ((4 * t) ^ (4 * (lane & 7))));
            out[ob + (size_t)(3 + 4 * t + 0) * K + lane] = v.x;
            out[ob + (size_t)(3 + 4 * t + 1) * K + lane] = v.y;
            out[ob + (size_t)(3 + 4 * t + 2) * K + lane] = v.z;
            out[ob + (size_t)(3 + 4 * t + 3) * K + lane] = v.w;
        }

        // Output dtype is float32: idx stored as float (0..8191 exact).
        out[FEAT_ELEMS + (size_t)m * K + lane] = empty ? 0.0f : (float)i;
        __syncwarp();
    }
}

extern "C" void kernel_launch(void* const* d_in, const int* in_sizes, int n_in,
                              void* d_out, int out_size)
{
    const float* xyz      = (const float*)d_in[0];
    // d_in[1]: xyz_batch_cnt (constant N_PER, unused)
    const float* new_xyz  = (const float*)d_in[2];
    // d_in[3]: new_xyz_batch_cnt (constant M_PER, unused)
    const float* features = (const float*)d_in[4];

    cudaFuncSetAttribute(sqag_kernel,
                         cudaFuncAttributeMaxDynamicSharedMemorySize, SMEM_BYTES);

    dim3 grid(CHUNKS, BATCHES);
    sqag_kernel<<<grid, THREADS, SMEM_BYTES>>>(xyz, new_xyz, features, (float*)d_out);
}